// round 1
// baseline (speedup 1.0000x reference)
#include <cuda_runtime.h>
#include <math.h>

#define BDIM   4
#define NTOK   2048
#define FEATC  256
#define HIDC   256
#define NHEADS 4
#define DHEAD  64
#define MROWS  (BDIM*NTOK)           // 8192 token rows per side
#define QK_SCALE 0.35355339059327373f  // DH^-0.25 (applied to both qk0 and qk1)

// ---------------- scratch (no allocations allowed) ----------------
__device__ float g_qk0[MROWS*HIDC];
__device__ float g_qk1[MROWS*HIDC];
__device__ float g_v0 [MROWS*HIDC];
__device__ float g_v1 [MROWS*HIDC];
__device__ float g_m0 [MROWS*HIDC];
__device__ float g_m1 [MROWS*HIDC];
__device__ float g_p0 [MROWS*HIDC];
__device__ float g_p1 [MROWS*HIDC];
__device__ float g_h0 [MROWS*2*FEATC];
__device__ float g_h1 [MROWS*2*FEATC];

#define EPI_PLAIN 0
#define EPI_HEAD  1
#define EPI_RES   2

// ---------------------------------------------------------------------------
// Generic register-tiled fp32 GEMM:  C[M,N] = epi( A_eff[M,K] @ W[N,K]^T + b )
//   A_eff: plain A (lda=K), or concat [A | A2] (each width K1=256) when A2!=0
//   epi: PLAIN store [M,N]; HEAD -> scale + [B,H,N,DH] layout; RES -> +R
// Block: 256 threads (16x16), tile 64x64, K-step 16, 4x4 frag per thread.
// ---------------------------------------------------------------------------
__global__ __launch_bounds__(256) void gemm_kernel(
    const float* __restrict__ A, const float* __restrict__ A2, int K1,
    const float* __restrict__ W, const float* __restrict__ bias,
    float* __restrict__ C, const float* __restrict__ R,
    int K, int N, int epi, float scale)
{
    __shared__ float As[16*68];
    __shared__ float Ws[16*68];
    const int t   = threadIdx.x;
    const int tx  = t & 15, ty = t >> 4;
    const int m0g = blockIdx.x * 64;
    const int n0g = blockIdx.y * 64;
    const int ldA = A2 ? K1 : K;
    const int rowl = t >> 2;          // 0..63 tile row (A) / tile col (W)
    const int kq   = (t & 3) * 4;     // k sub-offset

    float acc[4][4];
#pragma unroll
    for (int r = 0; r < 4; r++)
#pragma unroll
        for (int c = 0; c < 4; c++) acc[r][c] = 0.f;

    for (int kc = 0; kc < K; kc += 16) {
        const int kg = kc + kq;
        const float* asrc = (A2 && kg >= K1)
            ? A2 + (size_t)(m0g + rowl) * K1 + (kg - K1)
            : A  + (size_t)(m0g + rowl) * ldA + kg;
        float4 av = *(const float4*)asrc;
        As[(kq+0)*68 + rowl] = av.x;
        As[(kq+1)*68 + rowl] = av.y;
        As[(kq+2)*68 + rowl] = av.z;
        As[(kq+3)*68 + rowl] = av.w;
        float4 wv = *(const float4*)(W + (size_t)(n0g + rowl) * K + kg);
        Ws[(kq+0)*68 + rowl] = wv.x;
        Ws[(kq+1)*68 + rowl] = wv.y;
        Ws[(kq+2)*68 + rowl] = wv.z;
        Ws[(kq+3)*68 + rowl] = wv.w;
        __syncthreads();
#pragma unroll
        for (int kk = 0; kk < 16; kk++) {
            float4 a = *(const float4*)&As[kk*68 + ty*4];
            float4 b = *(const float4*)&Ws[kk*68 + tx*4];
            float ar[4] = {a.x, a.y, a.z, a.w};
            float br[4] = {b.x, b.y, b.z, b.w};
#pragma unroll
            for (int r = 0; r < 4; r++)
#pragma unroll
                for (int c = 0; c < 4; c++) acc[r][c] += ar[r] * br[c];
        }
        __syncthreads();
    }

    const int cb = n0g + tx*4;
    float4 bv = *(const float4*)&bias[cb];
    const float bb[4] = {bv.x, bv.y, bv.z, bv.w};
#pragma unroll
    for (int r = 0; r < 4; r++) {
        const int row = m0g + ty*4 + r;
        float4 v;
        v.x = (acc[r][0] + bb[0]) * scale;
        v.y = (acc[r][1] + bb[1]) * scale;
        v.z = (acc[r][2] + bb[2]) * scale;
        v.w = (acc[r][3] + bb[3]) * scale;
        if (epi == EPI_HEAD) {
            const int b_ = row >> 11, nn = row & (NTOK-1);
            const int h_ = cb >> 6,  dd = cb & 63;
            *(float4*)&C[(((size_t)(b_*NHEADS + h_))*NTOK + nn)*DHEAD + dd] = v;
        } else if (epi == EPI_RES) {
            float4 rr = *(const float4*)&R[(size_t)row * N + cb];
            v.x += rr.x; v.y += rr.y; v.z += rr.z; v.w += rr.w;
            *(float4*)&C[(size_t)row * N + cb] = v;
        } else {
            *(float4*)&C[(size_t)row * N + cb] = v;
        }
    }
}

// ---------------------------------------------------------------------------
// Flash attention (fp32), symmetric: side 0 computes m0 = softmax(Q0 K1^T) V1,
// side 1 computes m1 = softmax(Q1 K0^T) V0. Q/K/V layout [B*H][NTOK][DH].
// Block: 256 threads, Ti=64 query rows, stream over 64-key tiles.
// Output written in merged layout [B][NTOK][HID].
// ---------------------------------------------------------------------------
__global__ __launch_bounds__(256) void attn_kernel(
    const float* __restrict__ qk0, const float* __restrict__ qk1,
    const float* __restrict__ v0,  const float* __restrict__ v1,
    float* __restrict__ m0, float* __restrict__ m1)
{
    extern __shared__ float sm[];
    float* Qt = sm;              // [64 d][68] transposed Q
    float* KP = sm + 64*68;      // Kt [d][j], reused as Pt [j][i]
    float* Vs = sm + 2*64*68;    // [j][68] V tile

    const float *Q, *Kp, *Vp; float* O;
    if (blockIdx.z == 0) { Q = qk0; Kp = qk1; Vp = v1; O = m0; }
    else                 { Q = qk1; Kp = qk0; Vp = v0; O = m1; }

    const int bh = blockIdx.y;
    const int i0 = blockIdx.x * 64;
    const float* Qb = Q  + (size_t)bh * NTOK * DHEAD;
    const float* Kb = Kp + (size_t)bh * NTOK * DHEAD;
    const float* Vb = Vp + (size_t)bh * NTOK * DHEAD;

    const int t = threadIdx.x;
    const int tx = t & 15, ty = t >> 4;
    const int lrow = t >> 4;       // 0..15
    const int ld4  = (t & 15) * 4; // 0..60

    // load Q tile transposed
#pragma unroll
    for (int p = 0; p < 4; p++) {
        const int r = p*16 + lrow;
        float4 q = *(const float4*)&Qb[(size_t)(i0 + r)*DHEAD + ld4];
        Qt[(ld4+0)*68 + r] = q.x;
        Qt[(ld4+1)*68 + r] = q.y;
        Qt[(ld4+2)*68 + r] = q.z;
        Qt[(ld4+3)*68 + r] = q.w;
    }

    float o[4][4];
#pragma unroll
    for (int r = 0; r < 4; r++)
#pragma unroll
        for (int c = 0; c < 4; c++) o[r][c] = 0.f;
    float rm[4] = {-1e30f, -1e30f, -1e30f, -1e30f};
    float rs[4] = {0.f, 0.f, 0.f, 0.f};

    for (int j0 = 0; j0 < NTOK; j0 += 64) {
        __syncthreads();   // prior PV reads of KP/Vs done (and Qt visible, 1st iter)
        // load K (transposed) and V tiles
#pragma unroll
        for (int p = 0; p < 4; p++) {
            const int r = p*16 + lrow;
            float4 k = *(const float4*)&Kb[(size_t)(j0 + r)*DHEAD + ld4];
            KP[(ld4+0)*68 + r] = k.x;
            KP[(ld4+1)*68 + r] = k.y;
            KP[(ld4+2)*68 + r] = k.z;
            KP[(ld4+3)*68 + r] = k.w;
            float4 v = *(const float4*)&Vb[(size_t)(j0 + r)*DHEAD + ld4];
            *(float4*)&Vs[r*68 + ld4] = v;
        }
        __syncthreads();

        // S = Q K^T  (4x4 frag per thread)
        float s[4][4];
#pragma unroll
        for (int r = 0; r < 4; r++)
#pragma unroll
            for (int c = 0; c < 4; c++) s[r][c] = 0.f;
#pragma unroll 8
        for (int d = 0; d < 64; d++) {
            float4 a = *(const float4*)&Qt[d*68 + ty*4];
            float4 b = *(const float4*)&KP[d*68 + tx*4];
            float ar[4] = {a.x, a.y, a.z, a.w};
            float br[4] = {b.x, b.y, b.z, b.w};
#pragma unroll
            for (int r = 0; r < 4; r++)
#pragma unroll
                for (int c = 0; c < 4; c++) s[r][c] += ar[r] * br[c];
        }

        // online softmax: each row owned by one 16-lane half-warp group
#pragma unroll
        for (int r = 0; r < 4; r++) {
            float tm = fmaxf(fmaxf(s[r][0], s[r][1]), fmaxf(s[r][2], s[r][3]));
#pragma unroll
            for (int off = 8; off > 0; off >>= 1)
                tm = fmaxf(tm, __shfl_xor_sync(0xffffffffu, tm, off));
            const float m = fmaxf(rm[r], tm);
            const float alpha = __expf(rm[r] - m);
            float ps = 0.f;
#pragma unroll
            for (int c = 0; c < 4; c++) { s[r][c] = __expf(s[r][c] - m); ps += s[r][c]; }
#pragma unroll
            for (int off = 8; off > 0; off >>= 1)
                ps += __shfl_xor_sync(0xffffffffu, ps, off);
            rs[r] = rs[r] * alpha + ps;
            rm[r] = m;
#pragma unroll
            for (int c = 0; c < 4; c++) o[r][c] *= alpha;
        }

        __syncthreads();   // done reading KP as Kt
        // store P transposed into KP: Pt[j][i]
#pragma unroll
        for (int r = 0; r < 4; r++)
#pragma unroll
            for (int c = 0; c < 4; c++)
                KP[(tx*4 + c)*68 + ty*4 + r] = s[r][c];
        __syncthreads();

        // O += P V
#pragma unroll 8
        for (int j = 0; j < 64; j++) {
            float4 a = *(const float4*)&KP[j*68 + ty*4];
            float4 b = *(const float4*)&Vs[j*68 + tx*4];
            float ar[4] = {a.x, a.y, a.z, a.w};
            float br[4] = {b.x, b.y, b.z, b.w};
#pragma unroll
            for (int r = 0; r < 4; r++)
#pragma unroll
                for (int c = 0; c < 4; c++) o[r][c] += ar[r] * br[c];
        }
    }

    const int b_ = bh >> 2, h_ = bh & 3;
#pragma unroll
    for (int r = 0; r < 4; r++) {
        const float inv = 1.0f / rs[r];
        float4 v;
        v.x = o[r][0]*inv; v.y = o[r][1]*inv; v.z = o[r][2]*inv; v.w = o[r][3]*inv;
        *(float4*)&O[((size_t)(b_*NTOK + i0 + ty*4 + r))*HIDC + h_*DHEAD + tx*4] = v;
    }
}

// ---------------------------------------------------------------------------
// Rowwise LayerNorm + exact GELU, in-place on h [MROWS, 512]. 128 thr/row.
// ---------------------------------------------------------------------------
__global__ __launch_bounds__(128) void ln_gelu_kernel(
    float* __restrict__ h0, float* __restrict__ h1,
    const float* __restrict__ gamma, const float* __restrict__ beta)
{
    float* row = (blockIdx.y ? h1 : h0) + (size_t)blockIdx.x * 512;
    const int t = threadIdx.x;
    float4 v = *(const float4*)&row[t*4];
    __shared__ float red[8];

    float s = v.x + v.y + v.z + v.w;
#pragma unroll
    for (int off = 16; off > 0; off >>= 1) s += __shfl_xor_sync(0xffffffffu, s, off);
    if ((t & 31) == 0) red[t >> 5] = s;
    __syncthreads();
    const float mean = (red[0] + red[1] + red[2] + red[3]) * (1.0f/512.0f);

    const float d0 = v.x - mean, d1 = v.y - mean, d2 = v.z - mean, d3 = v.w - mean;
    float q = d0*d0 + d1*d1 + d2*d2 + d3*d3;
#pragma unroll
    for (int off = 16; off > 0; off >>= 1) q += __shfl_xor_sync(0xffffffffu, q, off);
    if ((t & 31) == 0) red[4 + (t >> 5)] = q;
    __syncthreads();
    const float var = (red[4] + red[5] + red[6] + red[7]) * (1.0f/512.0f);
    const float rstd = rsqrtf(var + 1e-5f);

    float4 g4 = *(const float4*)&gamma[t*4];
    float4 b4 = *(const float4*)&beta[t*4];
    float y[4];
    y[0] = d0*rstd*g4.x + b4.x;
    y[1] = d1*rstd*g4.y + b4.y;
    y[2] = d2*rstd*g4.z + b4.z;
    y[3] = d3*rstd*g4.w + b4.w;
#pragma unroll
    for (int i = 0; i < 4; i++)
        y[i] = 0.5f * y[i] * (1.0f + erff(y[i] * 0.70710678118654752f));
    float4 out; out.x = y[0]; out.y = y[1]; out.z = y[2]; out.w = y[3];
    *(float4*)&row[t*4] = out;
}

// ---------------------------------------------------------------------------
extern "C" void kernel_launch(void* const* d_in, const int* in_sizes, int n_in,
                              void* d_out, int out_size)
{
    const float* x0    = (const float*)d_in[0];
    const float* x1    = (const float*)d_in[1];
    const float* Wqk   = (const float*)d_in[2];
    const float* bqk   = (const float*)d_in[3];
    const float* Wv    = (const float*)d_in[4];
    const float* bv    = (const float*)d_in[5];
    const float* Wp    = (const float*)d_in[6];
    const float* bp    = (const float*)d_in[7];
    const float* W1    = (const float*)d_in[8];
    const float* b1    = (const float*)d_in[9];
    const float* gamma = (const float*)d_in[10];
    const float* beta  = (const float*)d_in[11];
    const float* W2    = (const float*)d_in[12];
    const float* b2    = (const float*)d_in[13];
    float* out = (float*)d_out;

    float *qk0, *qk1, *v0, *v1, *m0, *m1, *p0, *p1, *h0, *h1;
    cudaGetSymbolAddress((void**)&qk0, g_qk0);
    cudaGetSymbolAddress((void**)&qk1, g_qk1);
    cudaGetSymbolAddress((void**)&v0,  g_v0);
    cudaGetSymbolAddress((void**)&v1,  g_v1);
    cudaGetSymbolAddress((void**)&m0,  g_m0);
    cudaGetSymbolAddress((void**)&m1,  g_m1);
    cudaGetSymbolAddress((void**)&p0,  g_p0);
    cudaGetSymbolAddress((void**)&p1,  g_p1);
    cudaGetSymbolAddress((void**)&h0,  g_h0);
    cudaGetSymbolAddress((void**)&h1,  g_h1);

    // QK / V projections -> head-major [B,H,N,DH] (qk pre-scaled by DH^-0.25)
    dim3 gp(MROWS/64, HIDC/64);
    gemm_kernel<<<gp, 256>>>(x0, nullptr, 0, Wqk, bqk, qk0, nullptr, FEATC, HIDC, EPI_HEAD, QK_SCALE);
    gemm_kernel<<<gp, 256>>>(x0, nullptr, 0, Wv,  bv,  v0,  nullptr, FEATC, HIDC, EPI_HEAD, 1.0f);
    gemm_kernel<<<gp, 256>>>(x1, nullptr, 0, Wqk, bqk, qk1, nullptr, FEATC, HIDC, EPI_HEAD, QK_SCALE);
    gemm_kernel<<<gp, 256>>>(x1, nullptr, 0, Wv,  bv,  v1,  nullptr, FEATC, HIDC, EPI_HEAD, 1.0f);

    // bidirectional flash attention (z=0: m0, z=1: m1), outputs merged layout
    const int attn_smem = 3 * 64 * 68 * 4;  // 52224 B
    cudaFuncSetAttribute(attn_kernel, cudaFuncAttributeMaxDynamicSharedMemorySize, attn_smem);
    attn_kernel<<<dim3(NTOK/64, BDIM*NHEADS, 2), 256, attn_smem>>>(qk0, qk1, v0, v1, m0, m1);

    // Wp projection
    gemm_kernel<<<gp, 256>>>(m0, nullptr, 0, Wp, bp, p0, nullptr, HIDC, HIDC, EPI_PLAIN, 1.0f);
    gemm_kernel<<<gp, 256>>>(m1, nullptr, 0, Wp, bp, p1, nullptr, HIDC, HIDC, EPI_PLAIN, 1.0f);

    // MLP in-proj on concat([x, p])
    dim3 g1g(MROWS/64, (2*FEATC)/64);
    gemm_kernel<<<g1g, 256>>>(x0, p0, FEATC, W1, b1, h0, nullptr, FEATC + HIDC, 2*FEATC, EPI_PLAIN, 1.0f);
    gemm_kernel<<<g1g, 256>>>(x1, p1, FEATC, W1, b1, h1, nullptr, FEATC + HIDC, 2*FEATC, EPI_PLAIN, 1.0f);

    // LayerNorm + GELU (in place)
    ln_gelu_kernel<<<dim3(MROWS, 2), 128>>>(h0, h1, gamma, beta);

    // MLP out-proj + residual -> outputs (out0 then out1)
    dim3 g2g(MROWS/64, FEATC/64);
    gemm_kernel<<<g2g, 256>>>(h0, nullptr, 0, W2, b2, out,                         x0, 2*FEATC, FEATC, EPI_RES, 1.0f);
    gemm_kernel<<<g2g, 256>>>(h1, nullptr, 0, W2, b2, out + (size_t)MROWS*FEATC,   x1, 2*FEATC, FEATC, EPI_RES, 1.0f);
}

// round 2
// speedup vs baseline: 2.5872x; 2.5872x over previous
#include <cuda_runtime.h>
#include <cuda_bf16.h>
#include <stdint.h>
#include <math.h>

#define BDIM   4
#define NTOK   2048
#define FEATC  256
#define HIDC   256
#define NHEADS 4
#define DHEAD  64
#define MROWS  (BDIM*NTOK)
#define QK_SCALE 0.35355339059327373f  // DH^-0.25

// ---------------- scratch ----------------
__device__ float g_qk0[MROWS*HIDC];
__device__ float g_qk1[MROWS*HIDC];
__device__ float g_v0 [MROWS*HIDC];
__device__ float g_v1 [MROWS*HIDC];
__device__ float g_m0 [MROWS*HIDC];
__device__ float g_m1 [MROWS*HIDC];
__device__ float g_p0 [MROWS*HIDC];
__device__ float g_p1 [MROWS*HIDC];
__device__ float g_h0 [MROWS*2*FEATC];
__device__ float g_h1 [MROWS*2*FEATC];

#define EPI_PLAIN 0
#define EPI_HEAD  1
#define EPI_RES   2

// ---------------- bf16 split + mma helpers ----------------
__device__ __forceinline__ void split2(float x, float y, unsigned &hi, unsigned &lo) {
    __nv_bfloat162 h;
    h.x = __float2bfloat16_rn(x);
    h.y = __float2bfloat16_rn(y);
    hi = *reinterpret_cast<unsigned*>(&h);
    __nv_bfloat162 l;
    l.x = __float2bfloat16_rn(x - __bfloat162float(h.x));
    l.y = __float2bfloat16_rn(y - __bfloat162float(h.y));
    lo = *reinterpret_cast<unsigned*>(&l);
}

__device__ __forceinline__ void mma_bf16(float* d, const unsigned* a, const unsigned* b) {
    asm volatile(
        "mma.sync.aligned.m16n8k16.row.col.f32.bf16.bf16.f32 "
        "{%0,%1,%2,%3}, {%4,%5,%6,%7}, {%8,%9}, {%0,%1,%2,%3};\n"
        : "+f"(d[0]), "+f"(d[1]), "+f"(d[2]), "+f"(d[3])
        : "r"(a[0]), "r"(a[1]), "r"(a[2]), "r"(a[3]), "r"(b[0]), "r"(b[1]));
}

__device__ __forceinline__ void mma3(float* d, const unsigned* ah, const unsigned* al,
                                     const unsigned* bh, const unsigned* bl) {
    mma_bf16(d, ah, bh);
    mma_bf16(d, al, bh);
    mma_bf16(d, ah, bl);
}

// A frag (m16n8k16): rows row0+g (+8), k-words kw0+q (+4)
__device__ __forceinline__ void ldA(unsigned* a, const unsigned* base, int row0, int ld,
                                    int kw0, int g, int q) {
    const unsigned* p = base + (row0 + g) * ld + kw0 + q;
    a[0] = p[0]; a[2] = p[4];
    p += 8 * ld;
    a[1] = p[0]; a[3] = p[4];
}
// B frag: row n0+g of [n][k] tile, k-words kw0+q (+4)
__device__ __forceinline__ void ldB(unsigned* b, const unsigned* base, int n0, int ld,
                                    int kw0, int g, int q) {
    const unsigned* p = base + (n0 + g) * ld + kw0 + q;
    b[0] = p[0]; b[1] = p[4];
}

// ---------------------------------------------------------------------------
// GEMM: C[M,N] = epi( A_eff[M,K] @ W[N,K]^T + b ), split-3 bf16 MMA, fp32 acc
// Block 256 thr (8 warps), tile 128x64x32. Warp: 32x32 (2 m16 x 4 n8).
// ---------------------------------------------------------------------------
#define GLDW 20   // smem words per row: 32 bf16 (16 words) + 4 pad
__global__ __launch_bounds__(256) void gemm_kernel(
    const float* __restrict__ A, const float* __restrict__ A2, int K1,
    const float* __restrict__ W, const float* __restrict__ bias,
    float* __restrict__ C, const float* __restrict__ R,
    int K, int N, int epi, float scale)
{
    __shared__ unsigned sAh[128*GLDW], sAl[128*GLDW], sBh[64*GLDW], sBl[64*GLDW];
    const int t = threadIdx.x, lane = t & 31, wid = t >> 5;
    const int g = lane >> 2, q = lane & 3;
    const int wm = wid >> 1, wn = wid & 1;
    const int m0g = blockIdx.x * 128, n0g = blockIdx.y * 64;
    const int ldA_ = A2 ? K1 : K;

    float acc[2][4][4];
#pragma unroll
    for (int mt = 0; mt < 2; mt++)
#pragma unroll
        for (int nt = 0; nt < 4; nt++)
#pragma unroll
            for (int i = 0; i < 4; i++) acc[mt][nt][i] = 0.f;

    for (int kc = 0; kc < K; kc += 32) {
#pragma unroll
        for (int i = 0; i < 4; i++) {
            int id = t + i * 256;
            int row = id >> 3, kq = (id & 7) * 4;
            int kg = kc + kq;
            const float* src = (A2 && kg >= K1)
                ? (A2 + (size_t)(m0g + row) * K1 + (kg - K1))
                : (A  + (size_t)(m0g + row) * ldA_ + kg);
            float4 v = *(const float4*)src;
            unsigned h0, l0, h1, l1;
            split2(v.x, v.y, h0, l0);
            split2(v.z, v.w, h1, l1);
            int w = row * GLDW + (kq >> 1);
            sAh[w] = h0; sAh[w+1] = h1;
            sAl[w] = l0; sAl[w+1] = l1;
        }
#pragma unroll
        for (int i = 0; i < 2; i++) {
            int id = t + i * 256;
            int row = id >> 3, kq = (id & 7) * 4;
            float4 v = *(const float4*)(W + (size_t)(n0g + row) * K + kc + kq);
            unsigned h0, l0, h1, l1;
            split2(v.x, v.y, h0, l0);
            split2(v.z, v.w, h1, l1);
            int w = row * GLDW + (kq >> 1);
            sBh[w] = h0; sBh[w+1] = h1;
            sBl[w] = l0; sBl[w+1] = l1;
        }
        __syncthreads();
#pragma unroll
        for (int ch = 0; ch < 2; ch++) {
            const int kw0 = ch * 8;
            unsigned ah[2][4], al[2][4], bh[4][2], bl[4][2];
#pragma unroll
            for (int mt = 0; mt < 2; mt++) {
                ldA(ah[mt], sAh, wm*32 + mt*16, GLDW, kw0, g, q);
                ldA(al[mt], sAl, wm*32 + mt*16, GLDW, kw0, g, q);
            }
#pragma unroll
            for (int nt = 0; nt < 4; nt++) {
                ldB(bh[nt], sBh, wn*32 + nt*8, GLDW, kw0, g, q);
                ldB(bl[nt], sBl, wn*32 + nt*8, GLDW, kw0, g, q);
            }
#pragma unroll
            for (int mt = 0; mt < 2; mt++)
#pragma unroll
                for (int nt = 0; nt < 4; nt++)
                    mma3(acc[mt][nt], ah[mt], al[mt], bh[nt], bl[nt]);
        }
        __syncthreads();
    }

#pragma unroll
    for (int mt = 0; mt < 2; mt++) {
#pragma unroll
        for (int nt = 0; nt < 4; nt++) {
            const int row = m0g + wm*32 + mt*16 + g;
            const int col = n0g + wn*32 + nt*8 + 2*q;
            const float b0 = bias[col], b1 = bias[col+1];
#pragma unroll
            for (int hh = 0; hh < 2; hh++) {
                const int rr = row + hh*8;
                float2 v2;
                v2.x = (acc[mt][nt][hh*2+0] + b0) * scale;
                v2.y = (acc[mt][nt][hh*2+1] + b1) * scale;
                if (epi == EPI_HEAD) {
                    const int b_ = rr >> 11, nn = rr & (NTOK-1);
                    const int h_ = col >> 6, dd = col & 63;
                    *(float2*)&C[(((size_t)(b_*NHEADS + h_))*NTOK + nn)*DHEAD + dd] = v2;
                } else if (epi == EPI_RES) {
                    float2 rv = *(const float2*)&R[(size_t)rr * N + col];
                    v2.x += rv.x; v2.y += rv.y;
                    *(float2*)&C[(size_t)rr * N + col] = v2;
                } else {
                    *(float2*)&C[(size_t)rr * N + col] = v2;
                }
            }
        }
    }
}

// ---------------------------------------------------------------------------
// Flash attention, split-3 bf16 MMA. Q tile 128 rows, KV tile 64, 8 warps;
// warp owns 16 rows x full 64 j, so softmax is quad-local shfl only.
// ---------------------------------------------------------------------------
#define ALD 36  // smem words per row: 64 bf16 (32 words) + 4 pad
#define QH_OFF 0
#define QL_OFF (128*ALD)
#define KH_OFF (2*128*ALD)
#define KL_OFF (KH_OFF + 64*ALD)
#define VH_OFF (KL_OFF + 64*ALD)
#define VL_OFF (VH_OFF + 64*ALD)
#define PH_OFF (VL_OFF + 64*ALD)
#define PL_OFF (PH_OFF + 128*ALD)
#define ATT_SMEM_BYTES ((PL_OFF + 128*ALD) * 4)   // 110592

__global__ __launch_bounds__(256, 2) void attn_kernel(
    const float* __restrict__ qk0, const float* __restrict__ qk1,
    const float* __restrict__ v0,  const float* __restrict__ v1,
    float* __restrict__ m0, float* __restrict__ m1)
{
    extern __shared__ unsigned smw[];
    unsigned* QhW = smw + QH_OFF;
    unsigned* QlW = smw + QL_OFF;
    unsigned* KhW = smw + KH_OFF;
    unsigned* KlW = smw + KL_OFF;
    unsigned* VhW = smw + VH_OFF;
    unsigned* VlW = smw + VL_OFF;
    unsigned* PhW = smw + PH_OFF;
    unsigned* PlW = smw + PL_OFF;

    const float *Q, *Kp, *Vp; float* O;
    if (blockIdx.z == 0) { Q = qk0; Kp = qk1; Vp = v1; O = m0; }
    else                 { Q = qk1; Kp = qk0; Vp = v0; O = m1; }

    const int bh = blockIdx.y;
    const int i0 = blockIdx.x * 128;
    const float* Qb = Q  + (size_t)bh * NTOK * DHEAD;
    const float* Kb = Kp + (size_t)bh * NTOK * DHEAD;
    const float* Vb = Vp + (size_t)bh * NTOK * DHEAD;

    const int t = threadIdx.x, lane = t & 31, wid = t >> 5;
    const int g = lane >> 2, q = lane & 3;
    const int wrow = wid * 16;

    // load + split Q tile (128 x 64)
#pragma unroll
    for (int i = 0; i < 8; i++) {
        int id = t + i * 256;
        int row = id >> 4, c4 = (id & 15) * 4;
        float4 v = *(const float4*)&Qb[(size_t)(i0 + row) * DHEAD + c4];
        unsigned h0, l0, h1, l1;
        split2(v.x, v.y, h0, l0);
        split2(v.z, v.w, h1, l1);
        int w = row * ALD + (c4 >> 1);
        QhW[w] = h0; QhW[w+1] = h1;
        QlW[w] = l0; QlW[w+1] = l1;
    }

    float o[8][4];
#pragma unroll
    for (int dt = 0; dt < 8; dt++)
#pragma unroll
        for (int i = 0; i < 4; i++) o[dt][i] = 0.f;
    float rm0 = -1e30f, rm1 = -1e30f, rs0 = 0.f, rs1 = 0.f;

    const uint32_t vh_sa = (uint32_t)__cvta_generic_to_shared(VhW);
    const uint32_t vl_sa = (uint32_t)__cvta_generic_to_shared(VlW);

    for (int j0 = 0; j0 < NTOK; j0 += 64) {
        __syncthreads();   // prev PV done before K/V overwrite (also orders Q on iter 0)
#pragma unroll
        for (int i = 0; i < 4; i++) {
            int id = t + i * 256;
            int row = id >> 4, c4 = (id & 15) * 4;
            int w = row * ALD + (c4 >> 1);
            unsigned h0, l0, h1, l1;
            float4 kv = *(const float4*)&Kb[(size_t)(j0 + row) * DHEAD + c4];
            split2(kv.x, kv.y, h0, l0);
            split2(kv.z, kv.w, h1, l1);
            KhW[w] = h0; KhW[w+1] = h1;
            KlW[w] = l0; KlW[w+1] = l1;
            float4 vv = *(const float4*)&Vb[(size_t)(j0 + row) * DHEAD + c4];
            split2(vv.x, vv.y, h0, l0);
            split2(vv.z, vv.w, h1, l1);
            VhW[w] = h0; VhW[w+1] = h1;
            VlW[w] = l0; VlW[w+1] = l1;
        }
        __syncthreads();

        // S = Q K^T
        float sf[8][4];
#pragma unroll
        for (int nt = 0; nt < 8; nt++)
#pragma unroll
            for (int i = 0; i < 4; i++) sf[nt][i] = 0.f;
#pragma unroll
        for (int ks = 0; ks < 4; ks++) {
            const int kw0 = ks * 8;
            unsigned qh[4], ql[4];
            ldA(qh, QhW, wrow, ALD, kw0, g, q);
            ldA(ql, QlW, wrow, ALD, kw0, g, q);
#pragma unroll
            for (int nt = 0; nt < 8; nt++) {
                unsigned kh[2], kl[2];
                ldB(kh, KhW, nt*8, ALD, kw0, g, q);
                ldB(kl, KlW, nt*8, ALD, kw0, g, q);
                mma3(sf[nt], qh, ql, kh, kl);
            }
        }

        // online softmax (rows g and g+8, quad-local)
        float mx0 = -1e30f, mx1 = -1e30f;
#pragma unroll
        for (int nt = 0; nt < 8; nt++) {
            mx0 = fmaxf(mx0, fmaxf(sf[nt][0], sf[nt][1]));
            mx1 = fmaxf(mx1, fmaxf(sf[nt][2], sf[nt][3]));
        }
        mx0 = fmaxf(mx0, __shfl_xor_sync(0xffffffffu, mx0, 1));
        mx0 = fmaxf(mx0, __shfl_xor_sync(0xffffffffu, mx0, 2));
        mx1 = fmaxf(mx1, __shfl_xor_sync(0xffffffffu, mx1, 1));
        mx1 = fmaxf(mx1, __shfl_xor_sync(0xffffffffu, mx1, 2));
        const float nm0 = fmaxf(rm0, mx0), nm1 = fmaxf(rm1, mx1);
        const float a0 = __expf(rm0 - nm0), a1 = __expf(rm1 - nm1);
        rm0 = nm0; rm1 = nm1;
        float s0 = 0.f, s1 = 0.f;
#pragma unroll
        for (int nt = 0; nt < 8; nt++) {
            sf[nt][0] = __expf(sf[nt][0] - nm0); s0 += sf[nt][0];
            sf[nt][1] = __expf(sf[nt][1] - nm0); s0 += sf[nt][1];
            sf[nt][2] = __expf(sf[nt][2] - nm1); s1 += sf[nt][2];
            sf[nt][3] = __expf(sf[nt][3] - nm1); s1 += sf[nt][3];
        }
        s0 += __shfl_xor_sync(0xffffffffu, s0, 1);
        s0 += __shfl_xor_sync(0xffffffffu, s0, 2);
        s1 += __shfl_xor_sync(0xffffffffu, s1, 1);
        s1 += __shfl_xor_sync(0xffffffffu, s1, 2);
        rs0 = rs0 * a0 + s0;
        rs1 = rs1 * a1 + s1;
#pragma unroll
        for (int dt = 0; dt < 8; dt++) {
            o[dt][0] *= a0; o[dt][1] *= a0;
            o[dt][2] *= a1; o[dt][3] *= a1;
        }

        // store P (split)
#pragma unroll
        for (int nt = 0; nt < 8; nt++) {
            unsigned h, l;
            split2(sf[nt][0], sf[nt][1], h, l);
            int w = (wrow + g) * ALD + nt*4 + q;
            PhW[w] = h; PlW[w] = l;
            split2(sf[nt][2], sf[nt][3], h, l);
            w += 8 * ALD;
            PhW[w] = h; PlW[w] = l;
        }
        __syncthreads();

        // O += P V  (V frags via ldmatrix.trans from [j][d] tile)
#pragma unroll
        for (int ks = 0; ks < 4; ks++) {
            const int kw0 = ks * 8;
            unsigned ph[4], pl[4];
            ldA(ph, PhW, wrow, ALD, kw0, g, q);
            ldA(pl, PlW, wrow, ALD, kw0, g, q);
            const uint32_t rowoff = (uint32_t)((ks*16 + (lane & 15)) * (ALD * 4));
#pragma unroll
            for (int dt = 0; dt < 8; dt++) {
                unsigned vh[2], vl[2];
                asm volatile("ldmatrix.sync.aligned.m8n8.x2.trans.shared.b16 {%0,%1}, [%2];"
                    : "=r"(vh[0]), "=r"(vh[1]) : "r"(vh_sa + rowoff + dt*16));
                asm volatile("ldmatrix.sync.aligned.m8n8.x2.trans.shared.b16 {%0,%1}, [%2];"
                    : "=r"(vl[0]), "=r"(vl[1]) : "r"(vl_sa + rowoff + dt*16));
                mma3(o[dt], ph, pl, vh, vl);
            }
        }
    }

    const float inv0 = 1.f / rs0, inv1 = 1.f / rs1;
    const int b_ = bh >> 2, h_ = bh & 3;
    const int r0 = i0 + wrow + g, r1 = r0 + 8;
#pragma unroll
    for (int dt = 0; dt < 8; dt++) {
        const int d = h_ * 64 + dt*8 + 2*q;
        float2 v;
        v.x = o[dt][0] * inv0; v.y = o[dt][1] * inv0;
        *(float2*)&O[((size_t)(b_ * NTOK + r0)) * HIDC + d] = v;
        v.x = o[dt][2] * inv1; v.y = o[dt][3] * inv1;
        *(float2*)&O[((size_t)(b_ * NTOK + r1)) * HIDC + d] = v;
    }
}

// ---------------------------------------------------------------------------
// Rowwise LayerNorm + exact GELU, in-place on h [MROWS, 512]. 128 thr/row.
// ---------------------------------------------------------------------------
__global__ __launch_bounds__(128) void ln_gelu_kernel(
    float* __restrict__ h0, float* __restrict__ h1,
    const float* __restrict__ gamma, const float* __restrict__ beta)
{
    float* row = (blockIdx.y ? h1 : h0) + (size_t)blockIdx.x * 512;
    const int t = threadIdx.x;
    float4 v = *(const float4*)&row[t*4];
    __shared__ float red[8];

    float s = v.x + v.y + v.z + v.w;
#pragma unroll
    for (int off = 16; off > 0; off >>= 1) s += __shfl_xor_sync(0xffffffffu, s, off);
    if ((t & 31) == 0) red[t >> 5] = s;
    __syncthreads();
    const float mean = (red[0] + red[1] + red[2] + red[3]) * (1.0f/512.0f);

    const float d0 = v.x - mean, d1 = v.y - mean, d2 = v.z - mean, d3 = v.w - mean;
    float qv = d0*d0 + d1*d1 + d2*d2 + d3*d3;
#pragma unroll
    for (int off = 16; off > 0; off >>= 1) qv += __shfl_xor_sync(0xffffffffu, qv, off);
    if ((t & 31) == 0) red[4 + (t >> 5)] = qv;
    __syncthreads();
    const float var = (red[4] + red[5] + red[6] + red[7]) * (1.0f/512.0f);
    const float rstd = rsqrtf(var + 1e-5f);

    float4 g4 = *(const float4*)&gamma[t*4];
    float4 b4 = *(const float4*)&beta[t*4];
    float y[4];
    y[0] = d0*rstd*g4.x + b4.x;
    y[1] = d1*rstd*g4.y + b4.y;
    y[2] = d2*rstd*g4.z + b4.z;
    y[3] = d3*rstd*g4.w + b4.w;
#pragma unroll
    for (int i = 0; i < 4; i++)
        y[i] = 0.5f * y[i] * (1.0f + erff(y[i] * 0.70710678118654752f));
    float4 out; out.x = y[0]; out.y = y[1]; out.z = y[2]; out.w = y[3];
    *(float4*)&row[t*4] = out;
}

// ---------------------------------------------------------------------------
extern "C" void kernel_launch(void* const* d_in, const int* in_sizes, int n_in,
                              void* d_out, int out_size)
{
    const float* x0    = (const float*)d_in[0];
    const float* x1    = (const float*)d_in[1];
    const float* Wqk   = (const float*)d_in[2];
    const float* bqk   = (const float*)d_in[3];
    const float* Wv    = (const float*)d_in[4];
    const float* bv    = (const float*)d_in[5];
    const float* Wp    = (const float*)d_in[6];
    const float* bp    = (const float*)d_in[7];
    const float* W1    = (const float*)d_in[8];
    const float* b1    = (const float*)d_in[9];
    const float* gamma = (const float*)d_in[10];
    const float* beta  = (const float*)d_in[11];
    const float* W2    = (const float*)d_in[12];
    const float* b2    = (const float*)d_in[13];
    float* out = (float*)d_out;

    float *qk0, *qk1, *v0, *v1, *m0, *m1, *p0, *p1, *h0, *h1;
    cudaGetSymbolAddress((void**)&qk0, g_qk0);
    cudaGetSymbolAddress((void**)&qk1, g_qk1);
    cudaGetSymbolAddress((void**)&v0,  g_v0);
    cudaGetSymbolAddress((void**)&v1,  g_v1);
    cudaGetSymbolAddress((void**)&m0,  g_m0);
    cudaGetSymbolAddress((void**)&m1,  g_m1);
    cudaGetSymbolAddress((void**)&p0,  g_p0);
    cudaGetSymbolAddress((void**)&p1,  g_p1);
    cudaGetSymbolAddress((void**)&h0,  g_h0);
    cudaGetSymbolAddress((void**)&h1,  g_h1);

    // projections -> [B,H,N,DH]; qk pre-scaled by DH^-0.25
    dim3 gp(MROWS/128, HIDC/64);
    gemm_kernel<<<gp, 256>>>(x0, nullptr, 0, Wqk, bqk, qk0, nullptr, FEATC, HIDC, EPI_HEAD, QK_SCALE);
    gemm_kernel<<<gp, 256>>>(x0, nullptr, 0, Wv,  bv,  v0,  nullptr, FEATC, HIDC, EPI_HEAD, 1.0f);
    gemm_kernel<<<gp, 256>>>(x1, nullptr, 0, Wqk, bqk, qk1, nullptr, FEATC, HIDC, EPI_HEAD, QK_SCALE);
    gemm_kernel<<<gp, 256>>>(x1, nullptr, 0, Wv,  bv,  v1,  nullptr, FEATC, HIDC, EPI_HEAD, 1.0f);

    // bidirectional flash attention -> merged [B,N,HID]
    cudaFuncSetAttribute(attn_kernel, cudaFuncAttributeMaxDynamicSharedMemorySize, ATT_SMEM_BYTES);
    attn_kernel<<<dim3(NTOK/128, BDIM*NHEADS, 2), 256, ATT_SMEM_BYTES>>>(qk0, qk1, v0, v1, m0, m1);

    // Wp projection
    gemm_kernel<<<gp, 256>>>(m0, nullptr, 0, Wp, bp, p0, nullptr, HIDC, HIDC, EPI_PLAIN, 1.0f);
    gemm_kernel<<<gp, 256>>>(m1, nullptr, 0, Wp, bp, p1, nullptr, HIDC, HIDC, EPI_PLAIN, 1.0f);

    // MLP in-proj on concat([x, p])
    dim3 g1g(MROWS/128, (2*FEATC)/64);
    gemm_kernel<<<g1g, 256>>>(x0, p0, FEATC, W1, b1, h0, nullptr, FEATC + HIDC, 2*FEATC, EPI_PLAIN, 1.0f);
    gemm_kernel<<<g1g, 256>>>(x1, p1, FEATC, W1, b1, h1, nullptr, FEATC + HIDC, 2*FEATC, EPI_PLAIN, 1.0f);

    // LayerNorm + GELU (in place)
    ln_gelu_kernel<<<dim3(MROWS, 2), 128>>>(h0, h1, gamma, beta);

    // MLP out-proj + residual
    dim3 g2g(MROWS/128, FEATC/64);
    gemm_kernel<<<g2g, 256>>>(h0, nullptr, 0, W2, b2, out,                       x0, 2*FEATC, FEATC, EPI_RES, 1.0f);
    gemm_kernel<<<g2g, 256>>>(h1, nullptr, 0, W2, b2, out + (size_t)MROWS*FEATC, x1, 2*FEATC, FEATC, EPI_RES, 1.0f);
}

// round 3
// speedup vs baseline: 4.2669x; 1.6493x over previous
#include <cuda_runtime.h>
#include <cuda_fp16.h>
#include <stdint.h>
#include <math.h>

#define BDIM   4
#define NTOK   2048
#define FEATC  256
#define HIDC   256
#define NHEADS 4
#define DHEAD  64
#define MROWS  (BDIM*NTOK)
// DH^-0.25 * sqrt(log2(e)) : folds softmax base-2 conversion into both q and k
#define QK_SCALE_L2 0.424660902f

// ---------------- scratch ----------------
__device__ __half g_qk0[MROWS*HIDC];
__device__ __half g_qk1[MROWS*HIDC];
__device__ __half g_v0 [MROWS*HIDC];
__device__ __half g_v1 [MROWS*HIDC];
__device__ __half g_m0 [MROWS*HIDC];
__device__ __half g_m1 [MROWS*HIDC];
__device__ __half g_p0 [MROWS*HIDC];
__device__ __half g_p1 [MROWS*HIDC];
__device__ float  g_h0 [MROWS*2*FEATC];
__device__ float  g_h1 [MROWS*2*FEATC];
__device__ __half g_hg0[MROWS*2*FEATC];
__device__ __half g_hg1[MROWS*2*FEATC];

#define EPI_HEAD_H  0
#define EPI_PLAIN_H 1
#define EPI_PLAIN_F 2
#define EPI_RES     3

// ---------------- mma / ldmatrix helpers ----------------
__device__ __forceinline__ void mma_f16(float* d, const unsigned* a, const unsigned* b) {
    asm volatile(
        "mma.sync.aligned.m16n8k16.row.col.f32.f16.f16.f32 "
        "{%0,%1,%2,%3}, {%4,%5,%6,%7}, {%8,%9}, {%0,%1,%2,%3};\n"
        : "+f"(d[0]), "+f"(d[1]), "+f"(d[2]), "+f"(d[3])
        : "r"(a[0]), "r"(a[1]), "r"(a[2]), "r"(a[3]), "r"(b[0]), "r"(b[1]));
}
__device__ __forceinline__ void ldsm4(unsigned* r, uint32_t a) {
    asm volatile("ldmatrix.sync.aligned.m8n8.x4.shared.b16 {%0,%1,%2,%3}, [%4];"
        : "=r"(r[0]), "=r"(r[1]), "=r"(r[2]), "=r"(r[3]) : "r"(a));
}
__device__ __forceinline__ void ldsm4t(unsigned* r, uint32_t a) {
    asm volatile("ldmatrix.sync.aligned.m8n8.x4.trans.shared.b16 {%0,%1,%2,%3}, [%4];"
        : "=r"(r[0]), "=r"(r[1]), "=r"(r[2]), "=r"(r[3]) : "r"(a));
}

// ---------------------------------------------------------------------------
// GEMM: C[M,N] = epi( A_eff[M,K] @ W[N,K]^T + b ), fp16 MMA, fp32 accumulate.
// A_eff: Af (fp32) | Ahp (fp16) | concat [Af(fp32, k<K1) | A2h(fp16, k>=K1)]
// Block 256 thr (8 warps), tile 128x64x32. Warp: 32x32 (2 m16 x 4 n8).
// ---------------------------------------------------------------------------
#define GLDW 20   // words per row: 16 (32 halfs) + 4 pad; rows 16B-aligned
__global__ __launch_bounds__(256) void gemm_kernel(
    const float* __restrict__ Af, const __half* __restrict__ Ahp,
    const __half* __restrict__ A2h, int K1,
    const float* __restrict__ W, const float* __restrict__ bias,
    float* __restrict__ Cf, __half* __restrict__ Ch, const float* __restrict__ R,
    int K, int N, int epi, float scale)
{
    __shared__ unsigned sA[128*GLDW], sB[64*GLDW];
    const int t = threadIdx.x, lane = t & 31, wid = t >> 5;
    const int g = lane >> 2, q = lane & 3;
    const int wm = wid >> 1, wn = wid & 1;
    const int m0g = blockIdx.x * 128, n0g = blockIdx.y * 64;
    const int aw = A2h ? K1 : K;

    const uint32_t sAb = (uint32_t)__cvta_generic_to_shared(sA);
    const uint32_t sBb = (uint32_t)__cvta_generic_to_shared(sB);
    const uint32_t aoff = (((lane & 15) * GLDW) + ((lane >> 4) << 2)) * 4;
    const uint32_t boff = (((lane & 7) + ((lane >> 4) << 3)) * GLDW + (((lane >> 3) & 1) << 2)) * 4;

    float acc[2][4][4];
#pragma unroll
    for (int mt = 0; mt < 2; mt++)
#pragma unroll
        for (int nt = 0; nt < 4; nt++)
#pragma unroll
            for (int i = 0; i < 4; i++) acc[mt][nt][i] = 0.f;

    for (int kc = 0; kc < K; kc += 32) {
#pragma unroll
        for (int i = 0; i < 4; i++) {
            int id = t + i * 256;
            int row = id >> 3, kq = (id & 7) * 4, kg = kc + kq;
            unsigned w0, w1;
            if (A2h && kg >= K1) {
                uint2 u = *(const uint2*)(A2h + (size_t)(m0g + row) * K1 + (kg - K1));
                w0 = u.x; w1 = u.y;
            } else if (Af) {
                float4 v = *(const float4*)(Af + (size_t)(m0g + row) * aw + kg);
                __half2 h0 = __floats2half2_rn(v.x, v.y);
                __half2 h1 = __floats2half2_rn(v.z, v.w);
                w0 = *(unsigned*)&h0; w1 = *(unsigned*)&h1;
            } else {
                uint2 u = *(const uint2*)(Ahp + (size_t)(m0g + row) * K + kg);
                w0 = u.x; w1 = u.y;
            }
            int wdx = row * GLDW + (kq >> 1);
            sA[wdx] = w0; sA[wdx + 1] = w1;
        }
#pragma unroll
        for (int i = 0; i < 2; i++) {
            int id = t + i * 256;
            int row = id >> 3, kq = (id & 7) * 4;
            float4 v = *(const float4*)(W + (size_t)(n0g + row) * K + kc + kq);
            __half2 h0 = __floats2half2_rn(v.x, v.y);
            __half2 h1 = __floats2half2_rn(v.z, v.w);
            int wdx = row * GLDW + (kq >> 1);
            sB[wdx] = *(unsigned*)&h0; sB[wdx + 1] = *(unsigned*)&h1;
        }
        __syncthreads();
#pragma unroll
        for (int ch = 0; ch < 2; ch++) {
            unsigned a0[4], a1[4], b0[4], b1[4];
            ldsm4(a0, sAb + (uint32_t)(((wm*32 +  0)*GLDW + ch*8) * 4) + aoff);
            ldsm4(a1, sAb + (uint32_t)(((wm*32 + 16)*GLDW + ch*8) * 4) + aoff);
            ldsm4(b0, sBb + (uint32_t)(((wn*32 +  0)*GLDW + ch*8) * 4) + boff);
            ldsm4(b1, sBb + (uint32_t)(((wn*32 + 16)*GLDW + ch*8) * 4) + boff);
            mma_f16(acc[0][0], a0, b0 + 0);
            mma_f16(acc[0][1], a0, b0 + 2);
            mma_f16(acc[0][2], a0, b1 + 0);
            mma_f16(acc[0][3], a0, b1 + 2);
            mma_f16(acc[1][0], a1, b0 + 0);
            mma_f16(acc[1][1], a1, b0 + 2);
            mma_f16(acc[1][2], a1, b1 + 0);
            mma_f16(acc[1][3], a1, b1 + 2);
        }
        __syncthreads();
    }

#pragma unroll
    for (int mt = 0; mt < 2; mt++) {
#pragma unroll
        for (int nt = 0; nt < 4; nt++) {
            const int row = m0g + wm*32 + mt*16 + g;
            const int col = n0g + wn*32 + nt*8 + 2*q;
            const float b0 = bias[col], b1 = bias[col + 1];
#pragma unroll
            for (int hh = 0; hh < 2; hh++) {
                const int rr = row + hh * 8;
                float vx = (acc[mt][nt][hh*2+0] + b0) * scale;
                float vy = (acc[mt][nt][hh*2+1] + b1) * scale;
                if (epi == EPI_HEAD_H) {
                    const int b_ = rr >> 11, nn = rr & (NTOK - 1);
                    const int h_ = col >> 6, dd = col & 63;
                    __half2 hv = __floats2half2_rn(vx, vy);
                    *(__half2*)&Ch[(((size_t)(b_*NHEADS + h_))*NTOK + nn)*DHEAD + dd] = hv;
                } else if (epi == EPI_PLAIN_H) {
                    __half2 hv = __floats2half2_rn(vx, vy);
                    *(__half2*)&Ch[(size_t)rr * N + col] = hv;
                } else if (epi == EPI_RES) {
                    float2 rv = *(const float2*)&R[(size_t)rr * N + col];
                    float2 v2; v2.x = vx + rv.x; v2.y = vy + rv.y;
                    *(float2*)&Cf[(size_t)rr * N + col] = v2;
                } else {
                    float2 v2; v2.x = vx; v2.y = vy;
                    *(float2*)&Cf[(size_t)rr * N + col] = v2;
                }
            }
        }
    }
}

// ---------------------------------------------------------------------------
// Flash attention, fp16 MMA. Q tile 128, KV tile 64, 8 warps.
// Q frags preloaded to registers; Q smem region reused for P.
// Softmax in base-2 (scale folded into projections).
// ---------------------------------------------------------------------------
#define ALD  36                 // words per row: 32 (64 halfs) + 4 pad (144B, 16B-aligned)
#define KOFF (128*ALD)
#define VOFF (192*ALD)

__global__ __launch_bounds__(256, 2) void attn_kernel(
    const __half* __restrict__ qk0, const __half* __restrict__ qk1,
    const __half* __restrict__ v0,  const __half* __restrict__ v1,
    __half* __restrict__ m0, __half* __restrict__ m1)
{
    __shared__ unsigned smw[256*ALD];   // 36 KB: QP[128] | K[64] | V[64]

    const __half *Q, *Kp, *Vp; __half* O;
    if (blockIdx.z == 0) { Q = qk0; Kp = qk1; Vp = v1; O = m0; }
    else                 { Q = qk1; Kp = qk0; Vp = v0; O = m1; }

    const int bh = blockIdx.y;
    const int i0 = blockIdx.x * 128;
    const __half* Qb = Q  + (size_t)bh * NTOK * DHEAD;
    const __half* Kb = Kp + (size_t)bh * NTOK * DHEAD;
    const __half* Vb = Vp + (size_t)bh * NTOK * DHEAD;

    const int t = threadIdx.x, lane = t & 31, wid = t >> 5;
    const int g = lane >> 2, q = lane & 3;
    const int wrow = wid * 16;

    const uint32_t sbase = (uint32_t)__cvta_generic_to_shared(smw);
    const uint32_t aoffA = (((lane & 15) * ALD) + ((lane >> 4) << 2)) * 4;
    const uint32_t boffA = (((lane & 7) + ((lane >> 4) << 3)) * ALD + (((lane >> 3) & 1) << 2)) * 4;
    const uint32_t voffA = ((lane & 15) * ALD) * 4 + ((lane >> 4) << 4);

    // stage Q tile (128 x 64 halfs)
#pragma unroll
    for (int i = 0; i < 4; i++) {
        int id = t + i * 256;
        int row = id >> 3, c8 = (id & 7) * 8;
        uint4 u = *(const uint4*)(Qb + (size_t)(i0 + row) * DHEAD + c8);
        *(uint4*)&smw[row * ALD + (c8 >> 1)] = u;
    }
    __syncthreads();

    // extract Q frags to registers (then QP region becomes P)
    unsigned qf[4][4];
#pragma unroll
    for (int ks = 0; ks < 4; ks++)
        ldsm4(qf[ks], sbase + (uint32_t)((wrow * ALD + ks * 8) * 4) + aoffA);

    float o[8][4];
#pragma unroll
    for (int dt = 0; dt < 8; dt++)
#pragma unroll
        for (int i = 0; i < 4; i++) o[dt][i] = 0.f;
    float rm0 = -1e30f, rm1 = -1e30f, rs0 = 0.f, rs1 = 0.f;

    for (int j0 = 0; j0 < NTOK; j0 += 64) {
        __syncthreads();   // prev PV reads done before K/V overwrite
#pragma unroll
        for (int i = 0; i < 2; i++) {
            int id = t + i * 256;
            int row = id >> 3, c8 = (id & 7) * 8;
            uint4 ku = *(const uint4*)(Kb + (size_t)(j0 + row) * DHEAD + c8);
            *(uint4*)&smw[KOFF + row * ALD + (c8 >> 1)] = ku;
            uint4 vu = *(const uint4*)(Vb + (size_t)(j0 + row) * DHEAD + c8);
            *(uint4*)&smw[VOFF + row * ALD + (c8 >> 1)] = vu;
        }
        __syncthreads();

        // S = Q K^T (base-2-scaled logits)
        float sf[8][4];
#pragma unroll
        for (int nt = 0; nt < 8; nt++)
#pragma unroll
            for (int i = 0; i < 4; i++) sf[nt][i] = 0.f;
#pragma unroll
        for (int ks = 0; ks < 4; ks++) {
#pragma unroll
            for (int ntp = 0; ntp < 4; ntp++) {
                unsigned kb[4];
                ldsm4(kb, sbase + (uint32_t)(((KOFF + ntp*16*ALD) + ks*8) * 4) + boffA);
                mma_f16(sf[2*ntp + 0], qf[ks], kb + 0);
                mma_f16(sf[2*ntp + 1], qf[ks], kb + 2);
            }
        }

        // online softmax (rows g, g+8; quad-local reductions)
        float mx0 = -1e30f, mx1 = -1e30f;
#pragma unroll
        for (int nt = 0; nt < 8; nt++) {
            mx0 = fmaxf(mx0, fmaxf(sf[nt][0], sf[nt][1]));
            mx1 = fmaxf(mx1, fmaxf(sf[nt][2], sf[nt][3]));
        }
        mx0 = fmaxf(mx0, __shfl_xor_sync(0xffffffffu, mx0, 1));
        mx0 = fmaxf(mx0, __shfl_xor_sync(0xffffffffu, mx0, 2));
        mx1 = fmaxf(mx1, __shfl_xor_sync(0xffffffffu, mx1, 1));
        mx1 = fmaxf(mx1, __shfl_xor_sync(0xffffffffu, mx1, 2));
        const float nm0 = fmaxf(rm0, mx0), nm1 = fmaxf(rm1, mx1);
        const float a0 = exp2f(rm0 - nm0), a1 = exp2f(rm1 - nm1);
        rm0 = nm0; rm1 = nm1;
        float s0 = 0.f, s1 = 0.f;
#pragma unroll
        for (int nt = 0; nt < 8; nt++) {
            sf[nt][0] = exp2f(sf[nt][0] - nm0); s0 += sf[nt][0];
            sf[nt][1] = exp2f(sf[nt][1] - nm0); s0 += sf[nt][1];
            sf[nt][2] = exp2f(sf[nt][2] - nm1); s1 += sf[nt][2];
            sf[nt][3] = exp2f(sf[nt][3] - nm1); s1 += sf[nt][3];
        }
        s0 += __shfl_xor_sync(0xffffffffu, s0, 1);
        s0 += __shfl_xor_sync(0xffffffffu, s0, 2);
        s1 += __shfl_xor_sync(0xffffffffu, s1, 1);
        s1 += __shfl_xor_sync(0xffffffffu, s1, 2);
        rs0 = rs0 * a0 + s0;
        rs1 = rs1 * a1 + s1;
#pragma unroll
        for (int dt = 0; dt < 8; dt++) {
            o[dt][0] *= a0; o[dt][1] *= a0;
            o[dt][2] *= a1; o[dt][3] *= a1;
        }

        // store P (fp16) into QP region — own warp's rows only
#pragma unroll
        for (int nt = 0; nt < 8; nt++) {
            __half2 hp = __floats2half2_rn(sf[nt][0], sf[nt][1]);
            smw[(wrow + g) * ALD + nt*4 + q] = *(unsigned*)&hp;
            hp = __floats2half2_rn(sf[nt][2], sf[nt][3]);
            smw[(wrow + g + 8) * ALD + nt*4 + q] = *(unsigned*)&hp;
        }
        __syncwarp();

        // O += P V
#pragma unroll
        for (int ks = 0; ks < 4; ks++) {
            unsigned pf[4];
            ldsm4(pf, sbase + (uint32_t)((wrow * ALD + ks * 8) * 4) + aoffA);
#pragma unroll
            for (int dtp = 0; dtp < 4; dtp++) {
                unsigned vb[4];
                ldsm4t(vb, sbase + (uint32_t)((VOFF + ks*16*ALD) * 4) + dtp*32 + voffA);
                mma_f16(o[2*dtp + 0], pf, vb + 0);
                mma_f16(o[2*dtp + 1], pf, vb + 2);
            }
        }
    }

    const float inv0 = 1.f / rs0, inv1 = 1.f / rs1;
    const int b_ = bh >> 2, h_ = bh & 3;
    const int r0 = i0 + wrow + g, r1 = r0 + 8;
#pragma unroll
    for (int dt = 0; dt < 8; dt++) {
        const int d = h_ * 64 + dt*8 + 2*q;
        __half2 hv = __floats2half2_rn(o[dt][0] * inv0, o[dt][1] * inv0);
        *(__half2*)&O[((size_t)(b_ * NTOK + r0)) * HIDC + d] = hv;
        hv = __floats2half2_rn(o[dt][2] * inv1, o[dt][3] * inv1);
        *(__half2*)&O[((size_t)(b_ * NTOK + r1)) * HIDC + d] = hv;
    }
}

// ---------------------------------------------------------------------------
// Rowwise LayerNorm + exact GELU: h(fp32)[M,512] -> hg(fp16). 128 thr/row.
// ---------------------------------------------------------------------------
__global__ __launch_bounds__(128) void ln_gelu_kernel(
    const float* __restrict__ h0, const float* __restrict__ h1,
    __half* __restrict__ hg0, __half* __restrict__ hg1,
    const float* __restrict__ gamma, const float* __restrict__ beta)
{
    const float* row = (blockIdx.y ? h1 : h0) + (size_t)blockIdx.x * 512;
    __half* rowo = (blockIdx.y ? hg1 : hg0) + (size_t)blockIdx.x * 512;
    const int t = threadIdx.x;
    float4 v = *(const float4*)&row[t*4];
    __shared__ float red[8];

    float s = v.x + v.y + v.z + v.w;
#pragma unroll
    for (int off = 16; off > 0; off >>= 1) s += __shfl_xor_sync(0xffffffffu, s, off);
    if ((t & 31) == 0) red[t >> 5] = s;
    __syncthreads();
    const float mean = (red[0] + red[1] + red[2] + red[3]) * (1.0f/512.0f);

    const float d0 = v.x - mean, d1 = v.y - mean, d2 = v.z - mean, d3 = v.w - mean;
    float qv = d0*d0 + d1*d1 + d2*d2 + d3*d3;
#pragma unroll
    for (int off = 16; off > 0; off >>= 1) qv += __shfl_xor_sync(0xffffffffu, qv, off);
    if ((t & 31) == 0) red[4 + (t >> 5)] = qv;
    __syncthreads();
    const float var = (red[4] + red[5] + red[6] + red[7]) * (1.0f/512.0f);
    const float rstd = rsqrtf(var + 1e-5f);

    float4 g4 = *(const float4*)&gamma[t*4];
    float4 b4 = *(const float4*)&beta[t*4];
    float y[4];
    y[0] = d0*rstd*g4.x + b4.x;
    y[1] = d1*rstd*g4.y + b4.y;
    y[2] = d2*rstd*g4.z + b4.z;
    y[3] = d3*rstd*g4.w + b4.w;
#pragma unroll
    for (int i = 0; i < 4; i++)
        y[i] = 0.5f * y[i] * (1.0f + erff(y[i] * 0.70710678118654752f));
    __half2 o0 = __floats2half2_rn(y[0], y[1]);
    __half2 o1 = __floats2half2_rn(y[2], y[3]);
    uint2 u; u.x = *(unsigned*)&o0; u.y = *(unsigned*)&o1;
    *(uint2*)&rowo[t*4] = u;
}

// ---------------------------------------------------------------------------
extern "C" void kernel_launch(void* const* d_in, const int* in_sizes, int n_in,
                              void* d_out, int out_size)
{
    const float* x0    = (const float*)d_in[0];
    const float* x1    = (const float*)d_in[1];
    const float* Wqk   = (const float*)d_in[2];
    const float* bqk   = (const float*)d_in[3];
    const float* Wv    = (const float*)d_in[4];
    const float* bv    = (const float*)d_in[5];
    const float* Wp    = (const float*)d_in[6];
    const float* bp    = (const float*)d_in[7];
    const float* W1    = (const float*)d_in[8];
    const float* b1    = (const float*)d_in[9];
    const float* gamma = (const float*)d_in[10];
    const float* beta  = (const float*)d_in[11];
    const float* W2    = (const float*)d_in[12];
    const float* b2    = (const float*)d_in[13];
    float* out = (float*)d_out;

    __half *qk0, *qk1, *v0, *v1, *m0, *m1, *p0, *p1, *hg0, *hg1;
    float *h0, *h1;
    cudaGetSymbolAddress((void**)&qk0, g_qk0);
    cudaGetSymbolAddress((void**)&qk1, g_qk1);
    cudaGetSymbolAddress((void**)&v0,  g_v0);
    cudaGetSymbolAddress((void**)&v1,  g_v1);
    cudaGetSymbolAddress((void**)&m0,  g_m0);
    cudaGetSymbolAddress((void**)&m1,  g_m1);
    cudaGetSymbolAddress((void**)&p0,  g_p0);
    cudaGetSymbolAddress((void**)&p1,  g_p1);
    cudaGetSymbolAddress((void**)&h0,  g_h0);
    cudaGetSymbolAddress((void**)&h1,  g_h1);
    cudaGetSymbolAddress((void**)&hg0, g_hg0);
    cudaGetSymbolAddress((void**)&hg1, g_hg1);

    // projections -> head-major fp16 [B,H,N,DH]; qk scaled by DH^-0.25*sqrt(log2e)
    dim3 gp(MROWS/128, HIDC/64);
    gemm_kernel<<<gp, 256>>>(x0, nullptr, nullptr, 0, Wqk, bqk, nullptr, qk0, nullptr, 256, 256, EPI_HEAD_H, QK_SCALE_L2);
    gemm_kernel<<<gp, 256>>>(x0, nullptr, nullptr, 0, Wv,  bv,  nullptr, v0,  nullptr, 256, 256, EPI_HEAD_H, 1.0f);
    gemm_kernel<<<gp, 256>>>(x1, nullptr, nullptr, 0, Wqk, bqk, nullptr, qk1, nullptr, 256, 256, EPI_HEAD_H, QK_SCALE_L2);
    gemm_kernel<<<gp, 256>>>(x1, nullptr, nullptr, 0, Wv,  bv,  nullptr, v1,  nullptr, 256, 256, EPI_HEAD_H, 1.0f);

    // bidirectional flash attention -> merged fp16 [B,N,HID]
    attn_kernel<<<dim3(NTOK/128, BDIM*NHEADS, 2), 256>>>(qk0, qk1, v0, v1, m0, m1);

    // Wp projection (fp16 in, fp16 out)
    gemm_kernel<<<gp, 256>>>(nullptr, m0, nullptr, 0, Wp, bp, nullptr, p0, nullptr, 256, 256, EPI_PLAIN_H, 1.0f);
    gemm_kernel<<<gp, 256>>>(nullptr, m1, nullptr, 0, Wp, bp, nullptr, p1, nullptr, 256, 256, EPI_PLAIN_H, 1.0f);

    // MLP in-proj on concat([x fp32 | p fp16]) -> h fp32
    dim3 g1g(MROWS/128, (2*FEATC)/64);
    gemm_kernel<<<g1g, 256>>>(x0, nullptr, p0, FEATC, W1, b1, h0, nullptr, nullptr, FEATC + HIDC, 2*FEATC, EPI_PLAIN_F, 1.0f);
    gemm_kernel<<<g1g, 256>>>(x1, nullptr, p1, FEATC, W1, b1, h1, nullptr, nullptr, FEATC + HIDC, 2*FEATC, EPI_PLAIN_F, 1.0f);

    // LayerNorm + GELU -> hg fp16
    ln_gelu_kernel<<<dim3(MROWS, 2), 128>>>(h0, h1, hg0, hg1, gamma, beta);

    // MLP out-proj + residual -> fp32 outputs
    dim3 g2g(MROWS/128, FEATC/64);
    gemm_kernel<<<g2g, 256>>>(nullptr, hg0, nullptr, 0, W2, b2, out,                       nullptr, x0, 2*FEATC, FEATC, EPI_RES, 1.0f);
    gemm_kernel<<<g2g, 256>>>(nullptr, hg1, nullptr, 0, W2, b2, out + (size_t)MROWS*FEATC, nullptr, x1, 2*FEATC, FEATC, EPI_RES, 1.0f);
}

// round 4
// speedup vs baseline: 6.2287x; 1.4598x over previous
#include <cuda_runtime.h>
#include <cuda_fp16.h>
#include <stdint.h>
#include <math.h>

#define BDIM   4
#define NTOK   2048
#define FEATC  256
#define HIDC   256
#define NHEADS 4
#define DHEAD  64
#define MROWS  (BDIM*NTOK)
#define QK_SCALE_L2 0.424660902f   // DH^-0.25 * sqrt(log2 e)

// ---------------- scratch ----------------
__device__ __half g_qk0[MROWS*HIDC];
__device__ __half g_qk1[MROWS*HIDC];
__device__ __half g_v0 [MROWS*HIDC];
__device__ __half g_v1 [MROWS*HIDC];
__device__ __half g_m0 [MROWS*HIDC];
__device__ __half g_m1 [MROWS*HIDC];
__device__ __half g_cat0[MROWS*2*FEATC];   // [x fp16 | p fp16]
__device__ __half g_cat1[MROWS*2*FEATC];
__device__ float  g_h0 [MROWS*2*FEATC];
__device__ float  g_h1 [MROWS*2*FEATC];
__device__ __half g_hg0[MROWS*2*FEATC];
__device__ __half g_hg1[MROWS*2*FEATC];
__device__ __half g_wqk[HIDC*FEATC];
__device__ __half g_wv [HIDC*FEATC];
__device__ __half g_wp [HIDC*HIDC];
__device__ __half g_w1 [2*FEATC*(FEATC+HIDC)];
__device__ __half g_w2 [FEATC*2*FEATC];

#define EPI_HEAD_H  0
#define EPI_PLAIN_H 1
#define EPI_PLAIN_F 2
#define EPI_RES     3

// ---------------- asm helpers ----------------
__device__ __forceinline__ void mma_f16(float* d, const unsigned* a, const unsigned* b) {
    asm volatile(
        "mma.sync.aligned.m16n8k16.row.col.f32.f16.f16.f32 "
        "{%0,%1,%2,%3}, {%4,%5,%6,%7}, {%8,%9}, {%0,%1,%2,%3};\n"
        : "+f"(d[0]), "+f"(d[1]), "+f"(d[2]), "+f"(d[3])
        : "r"(a[0]), "r"(a[1]), "r"(a[2]), "r"(a[3]), "r"(b[0]), "r"(b[1]));
}
__device__ __forceinline__ void ldsm4(unsigned* r, uint32_t a) {
    asm volatile("ldmatrix.sync.aligned.m8n8.x4.shared.b16 {%0,%1,%2,%3}, [%4];"
        : "=r"(r[0]), "=r"(r[1]), "=r"(r[2]), "=r"(r[3]) : "r"(a));
}
__device__ __forceinline__ void ldsm4t(unsigned* r, uint32_t a) {
    asm volatile("ldmatrix.sync.aligned.m8n8.x4.trans.shared.b16 {%0,%1,%2,%3}, [%4];"
        : "=r"(r[0]), "=r"(r[1]), "=r"(r[2]), "=r"(r[3]) : "r"(a));
}
__device__ __forceinline__ void cpa16(uint32_t dst, const void* src) {
    asm volatile("cp.async.cg.shared.global [%0], [%1], 16;" :: "r"(dst), "l"(src));
}
__device__ __forceinline__ void cp_commit() { asm volatile("cp.async.commit_group;"); }
__device__ __forceinline__ void cp_wait1() { asm volatile("cp.async.wait_group 1;"); }

// ---------------------------------------------------------------------------
// fp32 -> fp16 conversions (x into cat[:, :256], weights flat)
// ---------------------------------------------------------------------------
__global__ __launch_bounds__(256) void convert_kernel(
    const float* __restrict__ x0, const float* __restrict__ x1,
    __half* __restrict__ cat0, __half* __restrict__ cat1,
    const float* __restrict__ Wqk, const float* __restrict__ Wv,
    const float* __restrict__ Wp, const float* __restrict__ W1, const float* __restrict__ W2,
    __half* __restrict__ wqk, __half* __restrict__ wv, __half* __restrict__ wp,
    __half* __restrict__ w1, __half* __restrict__ w2)
{
    const int z = blockIdx.z;
    const long idx = (long)blockIdx.x * 256 + threadIdx.x;   // float4 units
    const float* src = nullptr; __half* dst = nullptr; long cnt = 0;
    bool strided = false;
    switch (z) {
        case 0: src = x0;  dst = cat0; cnt = MROWS*FEATC/4; strided = true; break;
        case 1: src = x1;  dst = cat1; cnt = MROWS*FEATC/4; strided = true; break;
        case 2: src = Wqk; dst = wqk;  cnt = HIDC*FEATC/4; break;
        case 3: src = Wv;  dst = wv;   cnt = HIDC*FEATC/4; break;
        case 4: src = Wp;  dst = wp;   cnt = HIDC*HIDC/4; break;
        case 5: src = W1;  dst = w1;   cnt = 2*FEATC*(FEATC+HIDC)/4; break;
        case 6: src = W2;  dst = w2;   cnt = FEATC*2*FEATC/4; break;
    }
    if (idx >= cnt) return;
    float4 v = *(const float4*)(src + idx*4);
    __half2 h0 = __floats2half2_rn(v.x, v.y);
    __half2 h1 = __floats2half2_rn(v.z, v.w);
    uint2 u; u.x = *(unsigned*)&h0; u.y = *(unsigned*)&h1;
    if (strided) {
        long row = idx >> 6, c = (idx & 63) * 4;   // 64 float4 per 256-wide row
        *(uint2*)(dst + row * 512 + c) = u;
    } else {
        *(uint2*)(dst + idx*4) = u;
    }
}

// ---------------------------------------------------------------------------
// GEMM: C = epi( A[M,K] @ W[N,K]^T + b ), fp16 in, fp32 acc, 3-stage cp.async.
// Block 256 thr, tile 128x64x32. blockIdx.z selects side (A0/A1, C0/C1, R0/R1).
// Dual-weight mode (Wb != null): blockIdx.y >= ytiles uses Wb/biasb/Cb/scaleb.
// ---------------------------------------------------------------------------
#define GLDW 20
#define SA_W (128*GLDW)
#define SST_W (SA_W + 64*GLDW)   // 3840 words / stage
__global__ __launch_bounds__(256) void gemm_kernel(
    const __half* __restrict__ A0, const __half* __restrict__ A1, int lda,
    const __half* __restrict__ Wa, const float* __restrict__ biasa,
    const __half* __restrict__ Wb, const float* __restrict__ biasb,
    void* C0v, void* C1v, void* Cb0v, void* Cb1v, int ldc, int coloff,
    const float* __restrict__ R0, const float* __restrict__ R1,
    int K, int ytiles, int epi, float scalea, float scaleb)
{
    __shared__ unsigned sm[3*SST_W];   // 46080 B
    const int t = threadIdx.x, lane = t & 31, wid = t >> 5;
    const int g = lane >> 2, q = lane & 3;
    const int wm = wid >> 1, wn = wid & 1;
    const int z = blockIdx.z;
    const bool second = (int)blockIdx.y >= ytiles;
    const int yy = second ? (blockIdx.y - ytiles) : blockIdx.y;
    const int m0g = blockIdx.x * 128, n0g = yy * 64;
    const __half* A = z ? A1 : A0;
    const __half* W = second ? Wb : Wa;
    const float* bias = second ? biasb : biasa;
    const float scale = second ? scaleb : scalea;
    void* Cv = second ? (z ? Cb1v : Cb0v) : (z ? C1v : C0v);
    const float* R = z ? R1 : R0;

    const uint32_t sb = (uint32_t)__cvta_generic_to_shared(sm);
    const uint32_t aoff = (((lane & 15) * GLDW) + ((lane >> 4) << 2)) * 4;
    const uint32_t boff = (((lane & 7) + ((lane >> 4) << 3)) * GLDW + (((lane >> 3) & 1) << 2)) * 4;

    const int nk = K >> 5;
    // per-thread cp.async slots
    const int ar0 = t >> 2, ach = t & 3;            // A: rows ar0, ar0+64
    // issue lambda
    auto issue = [&](int kt) {
        const uint32_t stb = sb + (uint32_t)((kt % 3) * SST_W) * 4;
        const int kc = kt << 5;
        cpa16(stb + (uint32_t)((ar0)*GLDW + ach*4)*4,      A + (size_t)(m0g + ar0)      * lda + kc + ach*8);
        cpa16(stb + (uint32_t)((ar0+64)*GLDW + ach*4)*4,   A + (size_t)(m0g + ar0 + 64) * lda + kc + ach*8);
        cpa16(stb + (uint32_t)(SA_W + ar0*GLDW + ach*4)*4, W + (size_t)(n0g + ar0)      * K   + kc + ach*8);
    };

    float acc[2][4][4];
#pragma unroll
    for (int mt = 0; mt < 2; mt++)
#pragma unroll
        for (int nt = 0; nt < 4; nt++)
#pragma unroll
            for (int i = 0; i < 4; i++) acc[mt][nt][i] = 0.f;

    issue(0); cp_commit();
    issue(1); cp_commit();

    for (int kt = 0; kt < nk; kt++) {
        cp_wait1();
        __syncthreads();
        if (kt + 2 < nk) issue(kt + 2);
        cp_commit();
        const uint32_t stb = sb + (uint32_t)((kt % 3) * SST_W) * 4;
#pragma unroll
        for (int ch = 0; ch < 2; ch++) {
            unsigned a0[4], a1[4], b0[4], b1[4];
            ldsm4(a0, stb + (uint32_t)(((wm*32 +  0)*GLDW + ch*8) * 4) + aoff);
            ldsm4(a1, stb + (uint32_t)(((wm*32 + 16)*GLDW + ch*8) * 4) + aoff);
            ldsm4(b0, stb + (uint32_t)((SA_W + (wn*32 +  0)*GLDW + ch*8) * 4) + boff);
            ldsm4(b1, stb + (uint32_t)((SA_W + (wn*32 + 16)*GLDW + ch*8) * 4) + boff);
            mma_f16(acc[0][0], a0, b0 + 0);
            mma_f16(acc[0][1], a0, b0 + 2);
            mma_f16(acc[0][2], a0, b1 + 0);
            mma_f16(acc[0][3], a0, b1 + 2);
            mma_f16(acc[1][0], a1, b0 + 0);
            mma_f16(acc[1][1], a1, b0 + 2);
            mma_f16(acc[1][2], a1, b1 + 0);
            mma_f16(acc[1][3], a1, b1 + 2);
        }
    }

#pragma unroll
    for (int mt = 0; mt < 2; mt++) {
#pragma unroll
        for (int nt = 0; nt < 4; nt++) {
            const int row = m0g + wm*32 + mt*16 + g;
            const int col = n0g + wn*32 + nt*8 + 2*q;
            const float b0 = bias[col], b1 = bias[col + 1];
#pragma unroll
            for (int hh = 0; hh < 2; hh++) {
                const int rr = row + hh * 8;
                float vx = (acc[mt][nt][hh*2+0] + b0) * scale;
                float vy = (acc[mt][nt][hh*2+1] + b1) * scale;
                if (epi == EPI_HEAD_H) {
                    const int b_ = rr >> 11, nn = rr & (NTOK - 1);
                    const int h_ = col >> 6, dd = col & 63;
                    __half2 hv = __floats2half2_rn(vx, vy);
                    *(__half2*)((__half*)Cv + (((size_t)(b_*NHEADS + h_))*NTOK + nn)*DHEAD + dd) = hv;
                } else if (epi == EPI_PLAIN_H) {
                    __half2 hv = __floats2half2_rn(vx, vy);
                    *(__half2*)((__half*)Cv + (size_t)rr * ldc + coloff + col) = hv;
                } else if (epi == EPI_RES) {
                    float2 rv = *(const float2*)&R[(size_t)rr * ldc + col];
                    float2 v2; v2.x = vx + rv.x; v2.y = vy + rv.y;
                    *(float2*)((float*)Cv + (size_t)rr * ldc + col) = v2;
                } else {
                    float2 v2; v2.x = vx; v2.y = vy;
                    *(float2*)((float*)Cv + (size_t)rr * ldc + col) = v2;
                }
            }
        }
    }
}

// ---------------------------------------------------------------------------
// Flash attention, fp16 MMA, 3-stage cp.async KV pipeline.
// Q tile 128, KV tile 64, 8 warps. Q frags in regs; QP smem region reused for P.
// ---------------------------------------------------------------------------
#define ALD  36
#define QP_W (128*ALD)            // 4608 words
#define AST_W (128*ALD)           // stage: K 64 rows + V 64 rows
#define ATT_SMEM ((QP_W + 3*AST_W) * 4)   // 73728 B

__global__ __launch_bounds__(256, 2) void attn_kernel(
    const __half* __restrict__ qk0, const __half* __restrict__ qk1,
    const __half* __restrict__ v0,  const __half* __restrict__ v1,
    __half* __restrict__ m0, __half* __restrict__ m1)
{
    extern __shared__ unsigned smw[];

    const __half *Q, *Kp, *Vp; __half* O;
    if (blockIdx.z == 0) { Q = qk0; Kp = qk1; Vp = v1; O = m0; }
    else                 { Q = qk1; Kp = qk0; Vp = v0; O = m1; }

    const int bh = blockIdx.y;
    const int i0 = blockIdx.x * 128;
    const __half* Qb = Q  + (size_t)bh * NTOK * DHEAD;
    const __half* Kb = Kp + (size_t)bh * NTOK * DHEAD;
    const __half* Vb = Vp + (size_t)bh * NTOK * DHEAD;

    const int t = threadIdx.x, lane = t & 31, wid = t >> 5;
    const int g = lane >> 2, q = lane & 3;
    const int wrow = wid * 16;

    const uint32_t sbase = (uint32_t)__cvta_generic_to_shared(smw);
    const uint32_t aoffA = (((lane & 15) * ALD) + ((lane >> 4) << 2)) * 4;
    const uint32_t boffA = (((lane & 7) + ((lane >> 4) << 3)) * ALD + (((lane >> 3) & 1) << 2)) * 4;
    const uint32_t voffA = ((lane & 15) * ALD) * 4 + ((lane >> 4) << 4);

    const int kvrow = t >> 3, kvch = t & 7;   // kvrow 0..31
    auto issue = [&](int jt) {
        const uint32_t stb = sbase + (uint32_t)(QP_W + (jt % 3) * AST_W) * 4;
        const int j0 = jt << 6;
#pragma unroll
        for (int i = 0; i < 4; i++) {
            const int idx = kvrow + i * 32;   // 0..127
            const __half* src = (idx < 64)
                ? (Kb + (size_t)(j0 + idx) * DHEAD + kvch*8)
                : (Vb + (size_t)(j0 + idx - 64) * DHEAD + kvch*8);
            cpa16(stb + (uint32_t)(idx*ALD + kvch*4)*4, src);
        }
    };

    issue(0); cp_commit();
    issue(1); cp_commit();

    // stage Q tile (plain loads), extract frags
#pragma unroll
    for (int i = 0; i < 4; i++) {
        int id = t + i * 256;
        int row = id >> 3, c8 = (id & 7) * 8;
        uint4 u = *(const uint4*)(Qb + (size_t)(i0 + row) * DHEAD + c8);
        *(uint4*)&smw[row * ALD + (c8 >> 1)] = u;
    }
    __syncthreads();
    unsigned qf[4][4];
#pragma unroll
    for (int ks = 0; ks < 4; ks++)
        ldsm4(qf[ks], sbase + (uint32_t)((wrow * ALD + ks * 8) * 4) + aoffA);

    float o[8][4];
#pragma unroll
    for (int dt = 0; dt < 8; dt++)
#pragma unroll
        for (int i = 0; i < 4; i++) o[dt][i] = 0.f;
    float rm0 = -1e30f, rm1 = -1e30f, rs0 = 0.f, rs1 = 0.f;

    const int njt = NTOK / 64;
    for (int jt = 0; jt < njt; jt++) {
        cp_wait1();
        __syncthreads();
        if (jt + 2 < njt) issue(jt + 2);
        cp_commit();
        const uint32_t kb0 = sbase + (uint32_t)(QP_W + (jt % 3) * AST_W) * 4;
        const uint32_t vb0 = kb0 + (uint32_t)(64*ALD)*4;

        // S = Q K^T
        float sf[8][4];
#pragma unroll
        for (int nt = 0; nt < 8; nt++)
#pragma unroll
            for (int i = 0; i < 4; i++) sf[nt][i] = 0.f;
#pragma unroll
        for (int ks = 0; ks < 4; ks++) {
#pragma unroll
            for (int ntp = 0; ntp < 4; ntp++) {
                unsigned kbf[4];
                ldsm4(kbf, kb0 + (uint32_t)((ntp*16*ALD + ks*8) * 4) + boffA);
                mma_f16(sf[2*ntp + 0], qf[ks], kbf + 0);
                mma_f16(sf[2*ntp + 1], qf[ks], kbf + 2);
            }
        }

        // online softmax (base-2)
        float mx0 = -1e30f, mx1 = -1e30f;
#pragma unroll
        for (int nt = 0; nt < 8; nt++) {
            mx0 = fmaxf(mx0, fmaxf(sf[nt][0], sf[nt][1]));
            mx1 = fmaxf(mx1, fmaxf(sf[nt][2], sf[nt][3]));
        }
        mx0 = fmaxf(mx0, __shfl_xor_sync(0xffffffffu, mx0, 1));
        mx0 = fmaxf(mx0, __shfl_xor_sync(0xffffffffu, mx0, 2));
        mx1 = fmaxf(mx1, __shfl_xor_sync(0xffffffffu, mx1, 1));
        mx1 = fmaxf(mx1, __shfl_xor_sync(0xffffffffu, mx1, 2));
        const float nm0 = fmaxf(rm0, mx0), nm1 = fmaxf(rm1, mx1);
        const float a0 = exp2f(rm0 - nm0), a1 = exp2f(rm1 - nm1);
        rm0 = nm0; rm1 = nm1;
        float s0 = 0.f, s1 = 0.f;
#pragma unroll
        for (int nt = 0; nt < 8; nt++) {
            sf[nt][0] = exp2f(sf[nt][0] - nm0); s0 += sf[nt][0];
            sf[nt][1] = exp2f(sf[nt][1] - nm0); s0 += sf[nt][1];
            sf[nt][2] = exp2f(sf[nt][2] - nm1); s1 += sf[nt][2];
            sf[nt][3] = exp2f(sf[nt][3] - nm1); s1 += sf[nt][3];
        }
        s0 += __shfl_xor_sync(0xffffffffu, s0, 1);
        s0 += __shfl_xor_sync(0xffffffffu, s0, 2);
        s1 += __shfl_xor_sync(0xffffffffu, s1, 1);
        s1 += __shfl_xor_sync(0xffffffffu, s1, 2);
        rs0 = rs0 * a0 + s0;
        rs1 = rs1 * a1 + s1;
#pragma unroll
        for (int dt = 0; dt < 8; dt++) {
            o[dt][0] *= a0; o[dt][1] *= a0;
            o[dt][2] *= a1; o[dt][3] *= a1;
        }

        // store P (warp-private rows of QP region)
#pragma unroll
        for (int nt = 0; nt < 8; nt++) {
            __half2 hp = __floats2half2_rn(sf[nt][0], sf[nt][1]);
            smw[(wrow + g) * ALD + nt*4 + q] = *(unsigned*)&hp;
            hp = __floats2half2_rn(sf[nt][2], sf[nt][3]);
            smw[(wrow + g + 8) * ALD + nt*4 + q] = *(unsigned*)&hp;
        }
        __syncwarp();

        // O += P V
#pragma unroll
        for (int ks = 0; ks < 4; ks++) {
            unsigned pf[4];
            ldsm4(pf, sbase + (uint32_t)((wrow * ALD + ks * 8) * 4) + aoffA);
#pragma unroll
            for (int dtp = 0; dtp < 4; dtp++) {
                unsigned vb[4];
                ldsm4t(vb, vb0 + (uint32_t)((ks*16*ALD) * 4) + dtp*32 + voffA);
                mma_f16(o[2*dtp + 0], pf, vb + 0);
                mma_f16(o[2*dtp + 1], pf, vb + 2);
            }
        }
    }

    const float inv0 = 1.f / rs0, inv1 = 1.f / rs1;
    const int b_ = bh >> 2, h_ = bh & 3;
    const int r0 = i0 + wrow + g, r1 = r0 + 8;
#pragma unroll
    for (int dt = 0; dt < 8; dt++) {
        const int d = h_ * 64 + dt*8 + 2*q;
        __half2 hv = __floats2half2_rn(o[dt][0] * inv0, o[dt][1] * inv0);
        *(__half2*)&O[((size_t)(b_ * NTOK + r0)) * HIDC + d] = hv;
        hv = __floats2half2_rn(o[dt][2] * inv1, o[dt][3] * inv1);
        *(__half2*)&O[((size_t)(b_ * NTOK + r1)) * HIDC + d] = hv;
    }
}

// ---------------------------------------------------------------------------
// Rowwise LayerNorm + exact GELU: h(fp32)[M,512] -> hg(fp16). 128 thr/row.
// ---------------------------------------------------------------------------
__global__ __launch_bounds__(128) void ln_gelu_kernel(
    const float* __restrict__ h0, const float* __restrict__ h1,
    __half* __restrict__ hg0, __half* __restrict__ hg1,
    const float* __restrict__ gamma, const float* __restrict__ beta)
{
    const float* row = (blockIdx.y ? h1 : h0) + (size_t)blockIdx.x * 512;
    __half* rowo = (blockIdx.y ? hg1 : hg0) + (size_t)blockIdx.x * 512;
    const int t = threadIdx.x;
    float4 v = *(const float4*)&row[t*4];
    __shared__ float red[8];

    float s = v.x + v.y + v.z + v.w;
#pragma unroll
    for (int off = 16; off > 0; off >>= 1) s += __shfl_xor_sync(0xffffffffu, s, off);
    if ((t & 31) == 0) red[t >> 5] = s;
    __syncthreads();
    const float mean = (red[0] + red[1] + red[2] + red[3]) * (1.0f/512.0f);

    const float d0 = v.x - mean, d1 = v.y - mean, d2 = v.z - mean, d3 = v.w - mean;
    float qv = d0*d0 + d1*d1 + d2*d2 + d3*d3;
#pragma unroll
    for (int off = 16; off > 0; off >>= 1) qv += __shfl_xor_sync(0xffffffffu, qv, off);
    if ((t & 31) == 0) red[4 + (t >> 5)] = qv;
    __syncthreads();
    const float var = (red[4] + red[5] + red[6] + red[7]) * (1.0f/512.0f);
    const float rstd = rsqrtf(var + 1e-5f);

    float4 g4 = *(const float4*)&gamma[t*4];
    float4 b4 = *(const float4*)&beta[t*4];
    float y[4];
    y[0] = d0*rstd*g4.x + b4.x;
    y[1] = d1*rstd*g4.y + b4.y;
    y[2] = d2*rstd*g4.z + b4.z;
    y[3] = d3*rstd*g4.w + b4.w;
#pragma unroll
    for (int i = 0; i < 4; i++)
        y[i] = 0.5f * y[i] * (1.0f + erff(y[i] * 0.70710678118654752f));
    __half2 o0 = __floats2half2_rn(y[0], y[1]);
    __half2 o1 = __floats2half2_rn(y[2], y[3]);
    uint2 u; u.x = *(unsigned*)&o0; u.y = *(unsigned*)&o1;
    *(uint2*)&rowo[t*4] = u;
}

// ---------------------------------------------------------------------------
extern "C" void kernel_launch(void* const* d_in, const int* in_sizes, int n_in,
                              void* d_out, int out_size)
{
    const float* x0    = (const float*)d_in[0];
    const float* x1    = (const float*)d_in[1];
    const float* Wqk   = (const float*)d_in[2];
    const float* bqk   = (const float*)d_in[3];
    const float* Wv    = (const float*)d_in[4];
    const float* bv    = (const float*)d_in[5];
    const float* Wp    = (const float*)d_in[6];
    const float* bp    = (const float*)d_in[7];
    const float* W1    = (const float*)d_in[8];
    const float* b1    = (const float*)d_in[9];
    const float* gamma = (const float*)d_in[10];
    const float* beta  = (const float*)d_in[11];
    const float* W2    = (const float*)d_in[12];
    const float* b2    = (const float*)d_in[13];
    float* out = (float*)d_out;

    __half *qk0, *qk1, *v0, *v1, *m0, *m1, *cat0, *cat1, *hg0, *hg1;
    __half *wqk, *wv, *wp, *w1, *w2;
    float *h0, *h1;
    cudaGetSymbolAddress((void**)&qk0, g_qk0);
    cudaGetSymbolAddress((void**)&qk1, g_qk1);
    cudaGetSymbolAddress((void**)&v0,  g_v0);
    cudaGetSymbolAddress((void**)&v1,  g_v1);
    cudaGetSymbolAddress((void**)&m0,  g_m0);
    cudaGetSymbolAddress((void**)&m1,  g_m1);
    cudaGetSymbolAddress((void**)&cat0, g_cat0);
    cudaGetSymbolAddress((void**)&cat1, g_cat1);
    cudaGetSymbolAddress((void**)&h0,  g_h0);
    cudaGetSymbolAddress((void**)&h1,  g_h1);
    cudaGetSymbolAddress((void**)&hg0, g_hg0);
    cudaGetSymbolAddress((void**)&hg1, g_hg1);
    cudaGetSymbolAddress((void**)&wqk, g_wqk);
    cudaGetSymbolAddress((void**)&wv,  g_wv);
    cudaGetSymbolAddress((void**)&wp,  g_wp);
    cudaGetSymbolAddress((void**)&w1,  g_w1);
    cudaGetSymbolAddress((void**)&w2,  g_w2);

    // 1) fp32 -> fp16 conversions
    convert_kernel<<<dim3(2048, 1, 7), 256>>>(x0, x1, cat0, cat1,
        Wqk, Wv, Wp, W1, W2, wqk, wv, wp, w1, w2);

    // 2) fused projections: y<4 -> Wqk (scale) -> qk ; y>=4 -> Wv -> v
    gemm_kernel<<<dim3(MROWS/128, 8, 2), 256>>>(
        cat0, cat1, 512, wqk, bqk, wv, bv,
        qk0, qk1, v0, v1, 0, 0, nullptr, nullptr,
        FEATC, 4, EPI_HEAD_H, QK_SCALE_L2, 1.0f);

    // 3) bidirectional flash attention
    cudaFuncSetAttribute(attn_kernel, cudaFuncAttributeMaxDynamicSharedMemorySize, ATT_SMEM);
    attn_kernel<<<dim3(NTOK/128, BDIM*NHEADS, 2), 256, ATT_SMEM>>>(qk0, qk1, v0, v1, m0, m1);

    // 4) Wp projection -> cat[:, 256:]
    gemm_kernel<<<dim3(MROWS/128, 4, 2), 256>>>(
        m0, m1, 256, wp, bp, nullptr, nullptr,
        cat0, cat1, nullptr, nullptr, 512, 256, nullptr, nullptr,
        HIDC, 4, EPI_PLAIN_H, 1.0f, 1.0f);

    // 5) MLP in-proj (K=512) -> h fp32
    gemm_kernel<<<dim3(MROWS/128, 8, 2), 256>>>(
        cat0, cat1, 512, w1, b1, nullptr, nullptr,
        h0, h1, nullptr, nullptr, 512, 0, nullptr, nullptr,
        512, 8, EPI_PLAIN_F, 1.0f, 1.0f);

    // 6) LayerNorm + GELU -> hg fp16
    ln_gelu_kernel<<<dim3(MROWS, 2), 128>>>(h0, h1, hg0, hg1, gamma, beta);

    // 7) MLP out-proj + residual -> fp32 outputs
    gemm_kernel<<<dim3(MROWS/128, 4, 2), 256>>>(
        hg0, hg1, 512, w2, b2, nullptr, nullptr,
        out, out + (size_t)MROWS*FEATC, nullptr, nullptr, 256, 0, x0, x1,
        512, 4, EPI_RES, 1.0f, 1.0f);
}